// round 14
// baseline (speedup 1.0000x reference)
#include <cuda_runtime.h>
#include <cuda_fp16.h>
#include <math.h>

// ---------------------------------------------------------------------------
// GaussCrossEntropyLoss — heavy-first two-pass.
// Pass 1 (k_pass1): read pred+coord+segment ONCE (96 MB), compute
//                   c = CE*focal per point AND per-cloud z stats, write
//                   pack[i] = (f16(z)<<16)|f16(c)  (16 MB).
// Pass 2 (k_pass2): read pack only (16 MB, L2-hot), sum c * gauss_w(z, mu);
//                   last block writes the mean and resets state (no init).
// ---------------------------------------------------------------------------

#define FULLMASK 0xFFFFFFFFu
#define MAXB 8
#define BIGF 3.402823466e+38f
#define CAP  4194304

// Static initializers == clean state; the last k_pass2 block restores them.
__device__ float g_gmax[MAXB] = {-BIGF,-BIGF,-BIGF,-BIGF,-BIGF,-BIGF,-BIGF,-BIGF};
__device__ float g_pmin[MAXB] = { BIGF, BIGF, BIGF, BIGF, BIGF, BIGF, BIGF, BIGF};
__device__ float g_zmin[MAXB] = { BIGF, BIGF, BIGF, BIGF, BIGF, BIGF, BIGF, BIGF};
__device__ float g_zmax[MAXB] = {-BIGF,-BIGF,-BIGF,-BIGF,-BIGF,-BIGF,-BIGF,-BIGF};
__device__ float g_acc[32];
__device__ int   g_done;
__device__ unsigned int g_pack[CAP];

__device__ __forceinline__ void atomicMaxF(float* a, float v) {
    if (v >= 0.0f) atomicMax((int*)a, __float_as_int(v));
    else           atomicMin((unsigned int*)a, __float_as_uint(v));
}
__device__ __forceinline__ void atomicMinF(float* a, float v) {
    if (v >= 0.0f) atomicMin((int*)a, __float_as_int(v));
    else           atomicMax((unsigned int*)a, __float_as_uint(v));
}

__device__ __forceinline__ int batch_of(int i, const int* s_off) {
    int b = 0;
#pragma unroll
    for (int k = 0; k < MAXB; k++) b += (i >= s_off[k]);
    return b;
}

// c = cross-entropy * focal via logit margin (sigmoid form)
__device__ __forceinline__ float ce_focal(float x0, float x1, int s) {
    float dlt = s ? (x1 - x0) : (x0 - x1);
    dlt = fmaxf(dlt, -80.0f);
    float e   = __expf(-dlt);
    float r   = 1.0f + e;
    float inv = __frcp_rn(r);              // p_t
    float nlt = __logf(r);                 // -log p_t
    float om  = e * inv;                   // 1 - p_t
    return nlt * om * om;                  // CE * focal (alpha=1, gamma=2)
}

__device__ __forceinline__ unsigned int pack_zc(float z, float c) {
    unsigned int zh = __half_as_ushort(__float2half_rn(z));
    unsigned int ch = __half_as_ushort(__float2half_rn(c));
    return (zh << 16) | ch;
}

// branch-free asymmetric gaussian weight
__device__ __forceinline__ float gauss_w(float zz, float mu) {
    float d    = zz - mu;
    float dd   = d * d;
    float coef = (zz <= mu) ? -50.0f : -3.125f;
    float w    = __expf(coef * dd);
    return (d > 0.8f) ? 0.1f : w;
}

// ---------------------------------------------------------------------------
// Pass 1: heavy — full input stream, c-precompute, pack write, z stats.
// 8 points per thread, 12 front-batched LDG.128.
// ---------------------------------------------------------------------------
__global__ void __launch_bounds__(256)
k_pass1(const float* __restrict__ pred, const float* __restrict__ coord,
        const int* __restrict__ segment, const int* __restrict__ offset,
        int n, int nb, int usepack)
{
    __shared__ int   s_off[MAXB];
    __shared__ float s_gmax[MAXB], s_pmin[MAXB], s_zmin[MAXB], s_zmax[MAXB];
    const int tid = threadIdx.x;
    if (tid < MAXB) {
        s_off[tid]  = (tid < nb) ? offset[tid] : 0x7FFFFFFF;
        s_gmax[tid] = -BIGF;  s_pmin[tid] = BIGF;
        s_zmin[tid] =  BIGF;  s_zmax[tid] = -BIGF;
    }
    __syncthreads();

    const int t    = blockIdx.x * blockDim.x + tid;
    const int base = t * 8;
    const bool fullv = (base + 7 < n);

    float z[8];
    int   sg[8];
    int   b0 = 0;
    bool  uni = false;

    if (fullv) {
        // 12 independent LDG.128, front-batched
        const float4* p4 = (const float4*)pred;
        float4 p[4];
#pragma unroll
        for (int j = 0; j < 4; j++) p[j] = p4[4 * t + j];
        const float4* c4 = (const float4*)coord;
        float4 c[6];
#pragma unroll
        for (int j = 0; j < 6; j++) c[j] = c4[6 * t + j];
        const int4* s4 = (const int4*)segment;
        int4 sa = s4[2 * t], sb = s4[2 * t + 1];

        z[0]=c[0].z; z[1]=c[1].y; z[2]=c[2].x; z[3]=c[2].w;
        z[4]=c[3].z; z[5]=c[4].y; z[6]=c[5].x; z[7]=c[5].w;
        sg[0]=sa.x; sg[1]=sa.y; sg[2]=sa.z; sg[3]=sa.w;
        sg[4]=sb.x; sg[5]=sb.y; sg[6]=sb.z; sg[7]=sb.w;

        if (usepack) {
            unsigned int u[8];
#pragma unroll
            for (int j = 0; j < 4; j++) {
                float ca = ce_focal(p[j].x, p[j].y, sg[2*j]);
                float cb = ce_focal(p[j].z, p[j].w, sg[2*j+1]);
                u[2*j]   = pack_zc(z[2*j],   ca);
                u[2*j+1] = pack_zc(z[2*j+1], cb);
            }
            ((uint4*)g_pack)[2 * t + 0] = make_uint4(u[0], u[1], u[2], u[3]);
            ((uint4*)g_pack)[2 * t + 1] = make_uint4(u[4], u[5], u[6], u[7]);
        }

        b0  = batch_of(base, s_off);
        uni = (b0 == batch_of(base + 7, s_off));   // batch ids monotonic
    }

    const int  wb   = __shfl_sync(FULLMASK, b0, 0);
    const bool wuni = __all_sync(FULLMASK, fullv && uni && (b0 == wb));

    if (wuni) {
        float lg = -BIGF, lp = BIGF, lmn = BIGF, lmx = -BIGF;
#pragma unroll
        for (int j = 0; j < 8; j++) {
            float zz = z[j];
            if (sg[j] == 0) lg = fmaxf(lg, zz); else lp = fminf(lp, zz);
            lmn = fminf(lmn, zz);
            lmx = fmaxf(lmx, zz);
        }
#pragma unroll
        for (int o = 16; o > 0; o >>= 1) {
            lg  = fmaxf(lg,  __shfl_xor_sync(FULLMASK, lg,  o));
            lp  = fminf(lp,  __shfl_xor_sync(FULLMASK, lp,  o));
            lmn = fminf(lmn, __shfl_xor_sync(FULLMASK, lmn, o));
            lmx = fmaxf(lmx, __shfl_xor_sync(FULLMASK, lmx, o));
        }
        if ((tid & 31) == 0) {
            if (lg > -BIGF) atomicMaxF(&s_gmax[wb], lg);
            if (lp <  BIGF) atomicMinF(&s_pmin[wb], lp);
            atomicMinF(&s_zmin[wb], lmn);
            atomicMaxF(&s_zmax[wb], lmx);
        }
    } else {
#pragma unroll
        for (int j = 0; j < 8; j++) {
            int i = base + j;
            if (i < n) {
                float zz, cc; int ss;
                if (fullv) { zz = z[j]; ss = sg[j]; }
                else {
                    zz = coord[3 * i + 2];
                    ss = segment[i];
                    cc = ce_focal(pred[2 * i], pred[2 * i + 1], ss);
                    if (usepack) g_pack[i] = pack_zc(zz, cc);
                }
                int b = batch_of(i, s_off);
                if (ss == 0) atomicMaxF(&s_gmax[b], zz);
                else         atomicMinF(&s_pmin[b], zz);
                atomicMinF(&s_zmin[b], zz);
                atomicMaxF(&s_zmax[b], zz);
            }
        }
    }
    __syncthreads();

    if (tid < 32) {
        int b = tid >> 2, k = tid & 3;
        if      (k == 0) { float v = s_gmax[b]; if (v > -BIGF) atomicMaxF(&g_gmax[b], v); }
        else if (k == 1) { float v = s_pmin[b]; if (v <  BIGF) atomicMinF(&g_pmin[b], v); }
        else if (k == 2) { float v = s_zmin[b]; if (v <  BIGF) atomicMinF(&g_zmin[b], v); }
        else             { float v = s_zmax[b]; if (v > -BIGF) atomicMaxF(&g_zmax[b], v); }
    }
}

// ---------------------------------------------------------------------------
// Pass 2: light — pack only (16 MB), 16 points per thread, 4 LDG.128.
// ---------------------------------------------------------------------------
__global__ void __launch_bounds__(256)
k_pass2(const float* __restrict__ pred, const float* __restrict__ coord,
        const int* __restrict__ segment, const int* __restrict__ offset,
        float* __restrict__ out, int n, int nb, int nblocks, float inv_n,
        int usepack)
{
    __shared__ int   s_off[MAXB];
    __shared__ float s_mu[MAXB];
    __shared__ float s_part[8];
    const int tid = threadIdx.x;
    if (tid < MAXB) {
        s_off[tid] = (tid < nb) ? offset[tid] : 0x7FFFFFFF;
        float g = g_gmax[tid]; if (g <= -BIGF) g = g_zmin[tid];
        float p = g_pmin[tid]; if (p >=  BIGF) p = g_zmax[tid];
        s_mu[tid] = g + (p - g) * 0.5f;    // exact reference expression
    }
    __syncthreads();

    const int t    = blockIdx.x * blockDim.x + tid;
    const int base = t * 16;
    float acc = 0.0f;

    if (usepack && base + 15 < n) {
        uint4 ua = ((const uint4*)g_pack)[4 * t + 0];
        uint4 ub = ((const uint4*)g_pack)[4 * t + 1];
        uint4 uc = ((const uint4*)g_pack)[4 * t + 2];
        uint4 ud = ((const uint4*)g_pack)[4 * t + 3];
        unsigned int u[16] = { ua.x, ua.y, ua.z, ua.w,  ub.x, ub.y, ub.z, ub.w,
                               uc.x, uc.y, uc.z, uc.w,  ud.x, ud.y, ud.z, ud.w };
        int b0 = batch_of(base, s_off);
        if (b0 == batch_of(base + 15, s_off)) {
            const float mu = s_mu[b0];
#pragma unroll
            for (int j = 0; j < 16; j++) {
                __half2 h2 = *reinterpret_cast<__half2*>(&u[j]);
                float2  f  = __half22float2(h2);     // x = c, y = z
                acc = fmaf(f.x, gauss_w(f.y, mu), acc);
            }
        } else {
#pragma unroll
            for (int j = 0; j < 16; j++) {
                __half2 h2 = *reinterpret_cast<__half2*>(&u[j]);
                float2  f  = __half22float2(h2);
                int b = batch_of(base + j, s_off);
                acc = fmaf(f.x, gauss_w(f.y, s_mu[b]), acc);
            }
        }
    } else {
        // tail / fallback: scalar, recompute from raw inputs when not packed
        for (int j = 0; j < 16; j++) {
            int i = base + j;
            if (i < n) {
                float c, zz;
                if (usepack) {
                    unsigned int u = g_pack[i];
                    __half2 h2 = *reinterpret_cast<__half2*>(&u);
                    float2  f  = __half22float2(h2);
                    c = f.x; zz = f.y;
                } else {
                    zz = coord[3 * i + 2];
                    c  = ce_focal(pred[2 * i], pred[2 * i + 1], segment[i]);
                }
                int b = batch_of(i, s_off);
                acc = fmaf(c, gauss_w(zz, s_mu[b]), acc);
            }
        }
    }

#pragma unroll
    for (int o = 16; o > 0; o >>= 1)
        acc += __shfl_xor_sync(FULLMASK, acc, o);
    if ((tid & 31) == 0) s_part[tid >> 5] = acc;
    __syncthreads();

    if (tid == 0) {
        float s = 0.0f;
#pragma unroll
        for (int k = 0; k < 8; k++) s += s_part[k];
        atomicAdd(&g_acc[blockIdx.x & 31], s);
        __threadfence();
        int old = atomicAdd(&g_done, 1);
        if (old == nblocks - 1) {
            float tot = 0.0f;
#pragma unroll
            for (int k = 0; k < 32; k++)
                tot += *((volatile float*)&g_acc[k]);
            out[0] = tot * inv_n;
            // restore clean state for next graph replay
#pragma unroll
            for (int k = 0; k < 32; k++) g_acc[k] = 0.0f;
#pragma unroll
            for (int k = 0; k < MAXB; k++) {
                g_gmax[k] = -BIGF;  g_pmin[k] = BIGF;
                g_zmin[k] =  BIGF;  g_zmax[k] = -BIGF;
            }
            g_done = 0;
            __threadfence();
        }
    }
}

// ---------------------------------------------------------------------------
extern "C" void kernel_launch(void* const* d_in, const int* in_sizes, int n_in,
                              void* d_out, int out_size)
{
    const float* pred    = (const float*)d_in[0];
    const float* coord   = (const float*)d_in[1];
    const int*   segment = (const int*)d_in[2];
    const int*   offset  = (const int*)d_in[3];
    int n  = in_sizes[2];
    int nb = in_sizes[3]; if (nb > MAXB) nb = MAXB;
    int usepack = (n <= CAP) ? 1 : 0;

    const int threads = 256;
    const int blocks1 = (n + threads * 8  - 1) / (threads * 8);
    const int blocks2 = (n + threads * 16 - 1) / (threads * 16);

    k_pass1<<<blocks1, threads>>>(pred, coord, segment, offset, n, nb, usepack);
    k_pass2<<<blocks2, threads>>>(pred, coord, segment, offset,
                                  (float*)d_out, n, nb, blocks2,
                                  1.0f / (float)n, usepack);
}